// round 12
// baseline (speedup 1.0000x reference)
#include <cuda_runtime.h>
#include <cuda_fp16.h>
#include <math.h>
#include <stdint.h>

// Problem constants
#define BB 4
#define LL 2048
#define DD 512
#define HH 8
#define QDIM 64
#define FFD 2048
#define MTOT (BB*LL)          // 8192
#define EPS 1e-5f
#define ATT_SCALE 0.125f

// -------------------- scratch (device globals) ----------------------------
__device__ float  g_t1 [MTOT*DD];
__device__ float  g_zn [MTOT*DD];
__device__ float  g_o2 [MTOT*DD];
__device__ __half g_xh [MTOT*DD];
__device__ __half g_wqh[DD*DD];
__device__ __half g_wkh[DD*DD];
__device__ __half g_wvh[DD*DD];
__device__ __half g_wzh[DD*DD];
__device__ __half g_w1h[DD*FFD];
__device__ __half g_w2h[FFD*DD];
__device__ __half g_qh [MTOT*DD];
__device__ __half g_kh [MTOT*DD];
__device__ __half g_vh [MTOT*DD];
__device__ __half g_atth[MTOT*DD];
__device__ __half g_znh[MTOT*DD];
__device__ __half g_hh [MTOT*FFD];

// -------------------- PTX helpers -----------------------------------------
__device__ __forceinline__ void cp16h(__half* s, const __half* g) {
    uint32_t sa = (uint32_t)__cvta_generic_to_shared(s);
    asm volatile("cp.async.cg.shared.global [%0], [%1], 16;\n" :: "r"(sa), "l"(g));
}
__device__ __forceinline__ void cp_commit() { asm volatile("cp.async.commit_group;\n"); }
template<int N> __device__ __forceinline__ void cp_wait() {
    asm volatile("cp.async.wait_group %0;\n" :: "n"(N));
}
__device__ __forceinline__ uint32_t s2u(const void* p) {
    return (uint32_t)__cvta_generic_to_shared(p);
}
__device__ __forceinline__ void ldm4(uint32_t addr, uint32_t* r) {
    asm volatile("ldmatrix.sync.aligned.m8n8.x4.shared.b16 {%0,%1,%2,%3}, [%4];\n"
        : "=r"(r[0]), "=r"(r[1]), "=r"(r[2]), "=r"(r[3]) : "r"(addr));
}
__device__ __forceinline__ void ldm4t(uint32_t addr, uint32_t* r) {
    asm volatile("ldmatrix.sync.aligned.m8n8.x4.trans.shared.b16 {%0,%1,%2,%3}, [%4];\n"
        : "=r"(r[0]), "=r"(r[1]), "=r"(r[2]), "=r"(r[3]) : "r"(addr));
}
__device__ __forceinline__ void mma16(float* d, const uint32_t* a, uint32_t b0, uint32_t b1) {
    asm volatile("mma.sync.aligned.m16n8k16.row.col.f32.f16.f16.f32 "
        "{%0,%1,%2,%3}, {%4,%5,%6,%7}, {%8,%9}, {%0,%1,%2,%3};\n"
        : "+f"(d[0]), "+f"(d[1]), "+f"(d[2]), "+f"(d[3])
        : "r"(a[0]), "r"(a[1]), "r"(a[2]), "r"(a[3]), "r"(b0), "r"(b1));
}
__device__ __forceinline__ uint32_t h2u(__half2 h) { return *(uint32_t*)&h; }

// ===========================================================================
// fp16 GEMM (R5-proven config): C[M,N] = A[M,K]@B[K,N]. Block 128x128, BK=32,
// 3-stage cp.async, 256 threads, warp tile 64x32, one sync per k-iter.
// EPI: 0 = fp32 store, 1 = fp16 store, 2 = fp16 bias+relu store.
// ===========================================================================
#define GH_ALD 40
#define GH_BLD 136
#define GH_ASZ (128*GH_ALD)
#define GH_BSZ (32*GH_BLD)
#define GH_SMEM (3*(GH_ASZ+GH_BSZ)*2)

template<int EPI>
__device__ __forceinline__ void gemm_h_body(
    const __half* __restrict__ A, const __half* __restrict__ B,
    float* __restrict__ Cf, __half* __restrict__ Ch, const float* __restrict__ bias,
    int M, int N, int K, int mBase, int nBase)
{
    extern __shared__ __half hsm[];
    __half* As = hsm;
    __half* Bs = hsm + 3*GH_ASZ;
    const int tid = threadIdx.x, w = tid >> 5, lane = tid & 31;
    const int wm = w >> 2, wn = w & 3;
    const int g = lane >> 2, tig = lane & 3;

    auto load_stage = [&](int st, int k0) {
        __half* as = As + st*GH_ASZ;
        __half* bs = Bs + st*GH_BSZ;
        #pragma unroll
        for (int i=0;i<2;i++){
            int f = tid + i*256; int r = f>>2, c = f&3;
            cp16h(&as[r*GH_ALD + c*8], &A[(size_t)(mBase+r)*K + k0 + c*8]);
        }
        #pragma unroll
        for (int i=0;i<2;i++){
            int f = tid + i*256; int r = f>>4, c = f&15;
            cp16h(&bs[r*GH_BLD + c*8], &B[(size_t)(k0+r)*N + nBase + c*8]);
        }
        cp_commit();
    };

    float acc[4][4][4];
    #pragma unroll
    for (int mt=0;mt<4;mt++)
        #pragma unroll
        for (int nt=0;nt<4;nt++)
            #pragma unroll
            for (int e=0;e<4;e++) acc[mt][nt][e] = 0.f;

    const int nk = K/32;
    load_stage(0, 0);
    load_stage(1, 32);

    for (int kt=0; kt<nk; kt++){
        cp_wait<1>();
        __syncthreads();
        if (kt+2 < nk) load_stage((kt+2)%3, (kt+2)*32);

        uint32_t ab = s2u(As + (kt%3)*GH_ASZ);
        uint32_t bb = s2u(Bs + (kt%3)*GH_BSZ);
        #pragma unroll
        for (int ks=0; ks<2; ks++){
            uint32_t aw[4][4], bw[2][4];
            #pragma unroll
            for (int mt=0;mt<4;mt++)
                ldm4(ab + ((wm*64 + mt*16 + (lane&15))*GH_ALD + ks*16 + (lane>>4)*8)*2, aw[mt]);
            #pragma unroll
            for (int p=0;p<2;p++)
                ldm4t(bb + ((ks*16 + (lane&7) + ((lane>>3)&1)*8)*GH_BLD + wn*32 + p*16 + (lane>>4)*8)*2, bw[p]);
            #pragma unroll
            for (int mt=0;mt<4;mt++)
                #pragma unroll
                for (int p=0;p<2;p++){
                    mma16(acc[mt][2*p  ], aw[mt], bw[p][0], bw[p][1]);
                    mma16(acc[mt][2*p+1], aw[mt], bw[p][2], bw[p][3]);
                }
        }
        __syncthreads();
    }

    #pragma unroll
    for (int mt=0;mt<4;mt++)
        #pragma unroll
        for (int nt=0;nt<4;nt++){
            float* a = acc[mt][nt];
            int r = mBase + wm*64 + mt*16 + g;
            int c = nBase + wn*32 + nt*8 + 2*tig;
            if (EPI == 0){
                *(float2*)&Cf[(size_t)r*N + c]     = make_float2(a[0], a[1]);
                *(float2*)&Cf[(size_t)(r+8)*N + c] = make_float2(a[2], a[3]);
            } else if (EPI == 1){
                *(__half2*)&Ch[(size_t)r*N + c]     = __floats2half2_rn(a[0], a[1]);
                *(__half2*)&Ch[(size_t)(r+8)*N + c] = __floats2half2_rn(a[2], a[3]);
            } else {
                float2 bv = *(const float2*)&bias[c];
                *(__half2*)&Ch[(size_t)r*N + c] =
                    __floats2half2_rn(fmaxf(a[0]+bv.x,0.f), fmaxf(a[1]+bv.y,0.f));
                *(__half2*)&Ch[(size_t)(r+8)*N + c] =
                    __floats2half2_rn(fmaxf(a[2]+bv.x,0.f), fmaxf(a[3]+bv.y,0.f));
            }
        }
}

template<int EPI>
__global__ __launch_bounds__(256,2) void gemm_h(
    const __half* __restrict__ A, const __half* __restrict__ B,
    float* __restrict__ Cf, __half* __restrict__ Ch, const float* __restrict__ bias,
    int M, int N, int K)
{
    gemm_h_body<EPI>(A, B, Cf, Ch, bias, M, N, K, blockIdx.y*128, blockIdx.x*128);
}

__global__ __launch_bounds__(256,2) void gemm_qkv(
    const __half* __restrict__ A,
    const __half* __restrict__ B0, const __half* __restrict__ B1, const __half* __restrict__ B2,
    __half* __restrict__ C0, __half* __restrict__ C1, __half* __restrict__ C2,
    int M, int N, int K)
{
    const __half* B = (blockIdx.z==0) ? B0 : (blockIdx.z==1 ? B1 : B2);
    __half*       C = (blockIdx.z==0) ? C0 : (blockIdx.z==1 ? C1 : C2);
    gemm_h_body<1>(A, B, nullptr, C, nullptr, M, N, K, blockIdx.y*128, blockIdx.x*128);
}

// ===========================================================================
// FA2-style fp16 flash attention, 128-row Q tile (halves K/V L2 traffic).
// 256 threads (8 warps), warp = 16 q-rows. One __syncthreads per key tile.
// K/V tiles 64 keys, double-buffered. Reads separate qh/kh/vh (no packing).
// ===========================================================================
#define ATL 72
#define ATT_SMEM ((128 + 4*64)*ATL*2)   // Q 128 rows + 2x(K,V) 64 rows

__global__ __launch_bounds__(256) void attn_h_kernel(
    const __half* __restrict__ qh, const __half* __restrict__ kh,
    const __half* __restrict__ vh, __half* __restrict__ atth)
{
    extern __shared__ __half hsm[];
    __half* Qs = hsm;                                  // 128 x ATL
    __half* Ksb[2] = { hsm + 128*ATL,        hsm + (128+64)*ATL };
    __half* Vsb[2] = { hsm + (128+2*64)*ATL, hsm + (128+3*64)*ATL };

    const int tid = threadIdx.x, w = tid >> 5, lane = tid & 31;
    const int g = lane >> 2, tig = lane & 3;
    const int qtile = blockIdx.x, bh = blockIdx.y;
    const int b = bh >> 3, h = bh & 7;
    const size_t rowBase = (size_t)b * LL;
    const int colBase = h * QDIM;
    const int qrow0 = qtile * 128;
    const int NT = LL/64;

    auto loadKV = [&](int buf, int t) {
        #pragma unroll
        for (int i=0;i<2;i++){
            int f = tid + i*256; int r = f>>3, c = f&7;
            cp16h(&Ksb[buf][r*ATL + c*8], &kh[(rowBase + t*64 + r)*DD + colBase + c*8]);
            cp16h(&Vsb[buf][r*ATL + c*8], &vh[(rowBase + t*64 + r)*DD + colBase + c*8]);
        }
        cp_commit();
    };

    // Q tile 128x64 + first K/V -> smem (one group)
    #pragma unroll
    for (int i=0;i<4;i++){
        int f = tid + i*256; int r = f>>3, c = f&7;
        cp16h(&Qs[r*ATL + c*8], &qh[(rowBase + qrow0 + r)*DD + colBase + c*8]);
    }
    cp_commit();
    loadKV(0, 0);
    cp_wait<0>(); __syncthreads();

    // persistent Q A-fragments (warp w -> q rows w*16..w*16+15)
    uint32_t qb = s2u(Qs);
    uint32_t qf[4][4];
    #pragma unroll
    for (int ks=0;ks<4;ks++)
        ldm4(qb + ((w*16 + (lane&15))*ATL + ks*16 + (lane>>4)*8)*2, qf[ks]);

    float o[8][4];
    #pragma unroll
    for (int n=0;n<8;n++){ o[n][0]=o[n][1]=o[n][2]=o[n][3]=0.f; }
    float m0=-1e30f, m1=-1e30f, l0=0.f, l1=0.f;

    for (int kt=0; kt<NT; kt++){
        // issue next-tile load first (buffer freed by the sync at end of kt-1)
        if (kt+1 < NT) loadKV((kt+1)&1, kt+1);

        uint32_t kb = s2u(Ksb[kt&1]);
        uint32_t vb = s2u(Vsb[kt&1]);

        // S = Q @ K^T. K frag: (lane>>3)&1 -> dim half, lane>>4 -> key half
        float s[8][4];
        #pragma unroll
        for (int n=0;n<8;n++){ s[n][0]=s[n][1]=s[n][2]=s[n][3]=0.f; }
        #pragma unroll
        for (int ks=0;ks<4;ks++){
            uint32_t bw[4][4];
            #pragma unroll
            for (int p=0;p<4;p++)
                ldm4(kb + ((p*16 + (lane&7) + (lane>>4)*8)*ATL + ks*16 + ((lane>>3)&1)*8)*2, bw[p]);
            #pragma unroll
            for (int p=0;p<4;p++){
                mma16(s[2*p  ], qf[ks], bw[p][0], bw[p][1]);
                mma16(s[2*p+1], qf[ks], bw[p][2], bw[p][3]);
            }
        }

        // online softmax (rows g / g+8)
        float mx0=-1e30f, mx1=-1e30f;
        #pragma unroll
        for (int n=0;n<8;n++){
            mx0 = fmaxf(mx0, fmaxf(s[n][0], s[n][1]));
            mx1 = fmaxf(mx1, fmaxf(s[n][2], s[n][3]));
        }
        mx0 = fmaxf(mx0, __shfl_xor_sync(0xffffffffu, mx0, 1));
        mx0 = fmaxf(mx0, __shfl_xor_sync(0xffffffffu, mx0, 2));
        mx1 = fmaxf(mx1, __shfl_xor_sync(0xffffffffu, mx1, 1));
        mx1 = fmaxf(mx1, __shfl_xor_sync(0xffffffffu, mx1, 2));
        float nm0 = fmaxf(m0, mx0*ATT_SCALE);
        float nm1 = fmaxf(m1, mx1*ATT_SCALE);
        float a0 = __expf(m0 - nm0), a1 = __expf(m1 - nm1);
        float sum0 = 0.f, sum1 = 0.f;
        #pragma unroll
        for (int n=0;n<8;n++){
            s[n][0] = __expf(s[n][0]*ATT_SCALE - nm0);
            s[n][1] = __expf(s[n][1]*ATT_SCALE - nm0);
            s[n][2] = __expf(s[n][2]*ATT_SCALE - nm1);
            s[n][3] = __expf(s[n][3]*ATT_SCALE - nm1);
            sum0 += s[n][0] + s[n][1];
            sum1 += s[n][2] + s[n][3];
        }
        sum0 += __shfl_xor_sync(0xffffffffu, sum0, 1);
        sum0 += __shfl_xor_sync(0xffffffffu, sum0, 2);
        sum1 += __shfl_xor_sync(0xffffffffu, sum1, 1);
        sum1 += __shfl_xor_sync(0xffffffffu, sum1, 2);
        l0 = l0*a0 + sum0;  l1 = l1*a1 + sum1;
        m0 = nm0;  m1 = nm1;
        #pragma unroll
        for (int n=0;n<8;n++){
            o[n][0]*=a0; o[n][1]*=a0; o[n][2]*=a1; o[n][3]*=a1;
        }

        // O += P @ V  (P repacked from S accumulators, registers only)
        #pragma unroll
        for (int ks=0;ks<4;ks++){
            uint32_t pa[4];
            pa[0] = h2u(__floats2half2_rn(s[2*ks  ][0], s[2*ks  ][1]));
            pa[1] = h2u(__floats2half2_rn(s[2*ks  ][2], s[2*ks  ][3]));
            pa[2] = h2u(__floats2half2_rn(s[2*ks+1][0], s[2*ks+1][1]));
            pa[3] = h2u(__floats2half2_rn(s[2*ks+1][2], s[2*ks+1][3]));
            uint32_t vw[4][4];
            #pragma unroll
            for (int p=0;p<4;p++)
                ldm4t(vb + ((ks*16 + (lane&7) + ((lane>>3)&1)*8)*ATL + p*16 + (lane>>4)*8)*2, vw[p]);
            #pragma unroll
            for (int p=0;p<4;p++){
                mma16(o[2*p  ], pa, vw[p][0], vw[p][1]);
                mma16(o[2*p+1], pa, vw[p][2], vw[p][3]);
            }
        }

        // next tile resident + all warps done reading cur tile
        if (kt+1 < NT) cp_wait<0>();
        __syncthreads();
    }

    // normalize + store half
    float inv0 = 1.f/l0, inv1 = 1.f/l1;
    const size_t r0 = rowBase + qrow0 + w*16 + g;
    #pragma unroll
    for (int n=0;n<8;n++){
        *(__half2*)&atth[ r0     *DD + colBase + n*8 + 2*tig] =
            __floats2half2_rn(o[n][0]*inv0, o[n][1]*inv0);
        *(__half2*)&atth[(r0 + 8)*DD + colBase + n*8 + 2*tig] =
            __floats2half2_rn(o[n][2]*inv1, o[n][3]*inv1);
    }
}

// ===========================================================================
// LayerNorm over D=512 of (in + bias + resid); float4 vectorized.
// 128 threads, each owns one float4 (512 = 128*4). Optional fp16 copy out.
// ===========================================================================
__global__ __launch_bounds__(128) void ln_kernel(
    const float* __restrict__ in, const float* __restrict__ bias,
    const float* __restrict__ resid,
    const float* __restrict__ gamma, const float* __restrict__ beta,
    float* __restrict__ out, __half* __restrict__ out_h)
{
    __shared__ float sh[8];
    const int row = blockIdx.x;
    const size_t base = (size_t)row * DD;
    const int c = threadIdx.x * 4;

    float4 vi = *(const float4*)&in[base + c];
    float4 vb = *(const float4*)&bias[c];
    float4 vr = *(const float4*)&resid[base + c];
    float v0 = vi.x + vb.x + vr.x;
    float v1 = vi.y + vb.y + vr.y;
    float v2 = vi.z + vb.z + vr.z;
    float v3 = vi.w + vb.w + vr.w;

    float s = v0+v1+v2+v3;
    #pragma unroll
    for (int o=16;o>0;o>>=1) s += __shfl_xor_sync(0xffffffffu, s, o);
    if ((threadIdx.x & 31)==0) sh[threadIdx.x>>5] = s;
    __syncthreads();
    float mean = (sh[0]+sh[1]+sh[2]+sh[3]) * (1.0f/DD);
    float d0=v0-mean, d1=v1-mean, d2=v2-mean, d3=v3-mean;
    float sq = d0*d0 + d1*d1 + d2*d2 + d3*d3;
    #pragma unroll
    for (int o=16;o>0;o>>=1) sq += __shfl_xor_sync(0xffffffffu, sq, o);
    __syncthreads();
    if ((threadIdx.x & 31)==0) sh[4 + (threadIdx.x>>5)] = sq;
    __syncthreads();
    float var = (sh[4]+sh[5]+sh[6]+sh[7]) * (1.0f/DD);
    float rstd = rsqrtf(var + EPS);

    float4 vg = *(const float4*)&gamma[c];
    float4 vbeta = *(const float4*)&beta[c];
    float r0 = d0*rstd*vg.x + vbeta.x;
    float r1 = d1*rstd*vg.y + vbeta.y;
    float r2 = d2*rstd*vg.z + vbeta.z;
    float r3 = d3*rstd*vg.w + vbeta.w;
    *(float4*)&out[base + c] = make_float4(r0, r1, r2, r3);
    if (out_h){
        __half2 h0 = __floats2half2_rn(r0, r1);
        __half2 h1 = __floats2half2_rn(r2, r3);
        *(uint2*)&out_h[base + c] = make_uint2(h2u(h0), h2u(h1));
    }
}

// ===========================================================================
// fp32 -> fp16 convert: 7 tensors in one launch via blockIdx.y
// ===========================================================================
__global__ __launch_bounds__(256) void f2h7(
    const float* i0, __half* o0, int n0, const float* i1, __half* o1, int n1,
    const float* i2, __half* o2, int n2, const float* i3, __half* o3, int n3,
    const float* i4, __half* o4, int n4_, const float* i5, __half* o5, int n5,
    const float* i6, __half* o6, int n6)
{
    const float* in; __half* out; int n;
    switch (blockIdx.y){
        case 0: in=i0; out=o0; n=n0; break;
        case 1: in=i1; out=o1; n=n1; break;
        case 2: in=i2; out=o2; n=n2; break;
        case 3: in=i3; out=o3; n=n3; break;
        case 4: in=i4; out=o4; n=n4_; break;
        case 5: in=i5; out=o5; n=n5; break;
        default: in=i6; out=o6; n=n6; break;
    }
    int idx = blockIdx.x*256 + threadIdx.x;
    int q = n >> 2;
    if (idx < q){
        float4 v = ((const float4*)in)[idx];
        ((__half2*)out)[idx*2  ] = __floats2half2_rn(v.x, v.y);
        ((__half2*)out)[idx*2+1] = __floats2half2_rn(v.z, v.w);
    }
}

// ===========================================================================
extern "C" void kernel_launch(void* const* d_in, const int* in_sizes, int n_in,
                              void* d_out, int out_size)
{
    const float* x     = (const float*)d_in[0];
    const float* WQ    = (const float*)d_in[1];
    const float* WK    = (const float*)d_in[2];
    const float* WV    = (const float*)d_in[3];
    const float* WZ    = (const float*)d_in[4];
    const float* bZ    = (const float*)d_in[5];
    const float* W1    = (const float*)d_in[6];
    const float* b1    = (const float*)d_in[7];
    const float* W2    = (const float*)d_in[8];
    const float* b2    = (const float*)d_in[9];
    const float* gamma = (const float*)d_in[10];
    const float* beta  = (const float*)d_in[11];
    float* out = (float*)d_out;

    float  *t1, *zn, *o2;
    __half *xh,*wqh,*wkh,*wvh,*wzh,*w1h,*w2h,*qh,*kh,*vh,*atth,*znh,*hh;
    cudaGetSymbolAddress((void**)&t1,  g_t1);
    cudaGetSymbolAddress((void**)&zn,  g_zn);
    cudaGetSymbolAddress((void**)&o2,  g_o2);
    cudaGetSymbolAddress((void**)&xh,  g_xh);
    cudaGetSymbolAddress((void**)&wqh, g_wqh);
    cudaGetSymbolAddress((void**)&wkh, g_wkh);
    cudaGetSymbolAddress((void**)&wvh, g_wvh);
    cudaGetSymbolAddress((void**)&wzh, g_wzh);
    cudaGetSymbolAddress((void**)&w1h, g_w1h);
    cudaGetSymbolAddress((void**)&w2h, g_w2h);
    cudaGetSymbolAddress((void**)&qh,  g_qh);
    cudaGetSymbolAddress((void**)&kh,  g_kh);
    cudaGetSymbolAddress((void**)&vh,  g_vh);
    cudaGetSymbolAddress((void**)&atth,g_atth);
    cudaGetSymbolAddress((void**)&znh, g_znh);
    cudaGetSymbolAddress((void**)&hh,  g_hh);

    cudaFuncSetAttribute(gemm_h<0>, cudaFuncAttributeMaxDynamicSharedMemorySize, GH_SMEM);
    cudaFuncSetAttribute(gemm_h<2>, cudaFuncAttributeMaxDynamicSharedMemorySize, GH_SMEM);
    cudaFuncSetAttribute(gemm_qkv,  cudaFuncAttributeMaxDynamicSharedMemorySize, GH_SMEM);
    cudaFuncSetAttribute(attn_h_kernel, cudaFuncAttributeMaxDynamicSharedMemorySize, ATT_SMEM);

    // convert inputs + weights to fp16 (RN)
    f2h7<<<dim3(4096,7), 256>>>(
        x,  xh,  MTOT*DD,
        WQ, wqh, DD*DD,  WK, wkh, DD*DD,  WV, wvh, DD*DD,  WZ, wzh, DD*DD,
        W1, w1h, DD*FFD, W2, w2h, FFD*DD);

    // QKV projections -> fp16 q/k/v (3-way z batch)
    gemm_qkv<<<dim3(DD/128, MTOT/128, 3), 256, GH_SMEM>>>(
        xh, wqh, wkh, wvh, qh, kh, vh, MTOT, DD, DD);

    // flash attention -> fp16 att (128-row Q tiles)
    attn_h_kernel<<<dim3(LL/128, BB*HH), 256, ATT_SMEM>>>(qh, kh, vh, atth);

    // att @ WZ -> fp32 t1
    gemm_h<0><<<dim3(DD/128, MTOT/128), 256, GH_SMEM>>>(
        atth, wzh, t1, nullptr, nullptr, MTOT, DD, DD);

    // LN1: LN(t1 + bZ + x) -> zn (fp32) + znh (fp16)
    ln_kernel<<<MTOT, 128>>>(t1, bZ, x, gamma, beta, zn, znh);

    // FF1: zn @ W1 + b1, relu -> fp16 hh
    gemm_h<2><<<dim3(FFD/128, MTOT/128), 256, GH_SMEM>>>(
        znh, w1h, nullptr, hh, b1, MTOT, FFD, DD);

    // FF2: hh @ W2 -> fp32 o2
    gemm_h<0><<<dim3(DD/128, MTOT/128), 256, GH_SMEM>>>(
        hh, w2h, o2, nullptr, nullptr, MTOT, DD, FFD);

    // LN2: LN(o2 + b2 + zn) -> out
    ln_kernel<<<MTOT, 128>>>(o2, b2, zn, gamma, beta, out, nullptr);
}

// round 13
// speedup vs baseline: 1.0547x; 1.0547x over previous
#include <cuda_runtime.h>
#include <cuda_fp16.h>
#include <math.h>
#include <stdint.h>

// Problem constants
#define BB 4
#define LL 2048
#define DD 512
#define HH 8
#define QDIM 64
#define FFD 2048
#define MTOT (BB*LL)          // 8192
#define EPS 1e-5f
#define ATT_SCALE 0.125f

// -------------------- scratch (device globals) ----------------------------
__device__ float  g_t1 [MTOT*DD];
__device__ float  g_zn [MTOT*DD];
__device__ float  g_o2 [MTOT*DD];
__device__ __half g_xh [MTOT*DD];
__device__ __half g_wqh[DD*DD];
__device__ __half g_wkh[DD*DD];
__device__ __half g_wvh[DD*DD];
__device__ __half g_wzh[DD*DD];
__device__ __half g_w1h[DD*FFD];
__device__ __half g_w2h[FFD*DD];
__device__ __half g_qh [MTOT*DD];
__device__ __half g_kh [MTOT*DD];
__device__ __half g_vh [MTOT*DD];
__device__ __half g_atth[MTOT*DD];
__device__ __half g_znh[MTOT*DD];
__device__ __half g_hh [MTOT*FFD];

// -------------------- PTX helpers -----------------------------------------
__device__ __forceinline__ void cp16h(__half* s, const __half* g) {
    uint32_t sa = (uint32_t)__cvta_generic_to_shared(s);
    asm volatile("cp.async.cg.shared.global [%0], [%1], 16;\n" :: "r"(sa), "l"(g));
}
__device__ __forceinline__ void cp_commit() { asm volatile("cp.async.commit_group;\n"); }
template<int N> __device__ __forceinline__ void cp_wait() {
    asm volatile("cp.async.wait_group %0;\n" :: "n"(N));
}
__device__ __forceinline__ uint32_t s2u(const void* p) {
    return (uint32_t)__cvta_generic_to_shared(p);
}
__device__ __forceinline__ void ldm4(uint32_t addr, uint32_t* r) {
    asm volatile("ldmatrix.sync.aligned.m8n8.x4.shared.b16 {%0,%1,%2,%3}, [%4];\n"
        : "=r"(r[0]), "=r"(r[1]), "=r"(r[2]), "=r"(r[3]) : "r"(addr));
}
__device__ __forceinline__ void ldm4t(uint32_t addr, uint32_t* r) {
    asm volatile("ldmatrix.sync.aligned.m8n8.x4.trans.shared.b16 {%0,%1,%2,%3}, [%4];\n"
        : "=r"(r[0]), "=r"(r[1]), "=r"(r[2]), "=r"(r[3]) : "r"(addr));
}
__device__ __forceinline__ void mma16(float* d, const uint32_t* a, uint32_t b0, uint32_t b1) {
    asm volatile("mma.sync.aligned.m16n8k16.row.col.f32.f16.f16.f32 "
        "{%0,%1,%2,%3}, {%4,%5,%6,%7}, {%8,%9}, {%0,%1,%2,%3};\n"
        : "+f"(d[0]), "+f"(d[1]), "+f"(d[2]), "+f"(d[3])
        : "r"(a[0]), "r"(a[1]), "r"(a[2]), "r"(a[3]), "r"(b0), "r"(b1));
}
__device__ __forceinline__ uint32_t h2u(__half2 h) { return *(uint32_t*)&h; }

// ===========================================================================
// fp16 GEMM (R5-proven config): C[M,N] = A[M,K]@B[K,N]. Block 128x128, BK=32,
// 3-stage cp.async, 256 threads, warp tile 64x32.
// EPI: 0 = fp32 store, 1 = fp16 store, 2 = fp16 bias+relu store.
// ===========================================================================
#define GH_ALD 40
#define GH_BLD 136
#define GH_ASZ (128*GH_ALD)
#define GH_BSZ (32*GH_BLD)
#define GH_SMEM (3*(GH_ASZ+GH_BSZ)*2)

template<int EPI>
__device__ __forceinline__ void gemm_h_body(
    const __half* __restrict__ A, const __half* __restrict__ B,
    float* __restrict__ Cf, __half* __restrict__ Ch, const float* __restrict__ bias,
    int M, int N, int K, int mBase, int nBase)
{
    extern __shared__ __half hsm[];
    __half* As = hsm;
    __half* Bs = hsm + 3*GH_ASZ;
    const int tid = threadIdx.x, w = tid >> 5, lane = tid & 31;
    const int wm = w >> 2, wn = w & 3;
    const int g = lane >> 2, tig = lane & 3;

    auto load_stage = [&](int st, int k0) {
        __half* as = As + st*GH_ASZ;
        __half* bs = Bs + st*GH_BSZ;
        #pragma unroll
        for (int i=0;i<2;i++){
            int f = tid + i*256; int r = f>>2, c = f&3;
            cp16h(&as[r*GH_ALD + c*8], &A[(size_t)(mBase+r)*K + k0 + c*8]);
        }
        #pragma unroll
        for (int i=0;i<2;i++){
            int f = tid + i*256; int r = f>>4, c = f&15;
            cp16h(&bs[r*GH_BLD + c*8], &B[(size_t)(k0+r)*N + nBase + c*8]);
        }
        cp_commit();
    };

    float acc[4][4][4];
    #pragma unroll
    for (int mt=0;mt<4;mt++)
        #pragma unroll
        for (int nt=0;nt<4;nt++)
            #pragma unroll
            for (int e=0;e<4;e++) acc[mt][nt][e] = 0.f;

    const int nk = K/32;
    load_stage(0, 0);
    load_stage(1, 32);

    for (int kt=0; kt<nk; kt++){
        cp_wait<1>();
        __syncthreads();
        if (kt+2 < nk) load_stage((kt+2)%3, (kt+2)*32);

        uint32_t ab = s2u(As + (kt%3)*GH_ASZ);
        uint32_t bb = s2u(Bs + (kt%3)*GH_BSZ);
        #pragma unroll
        for (int ks=0; ks<2; ks++){
            uint32_t aw[4][4], bw[2][4];
            #pragma unroll
            for (int mt=0;mt<4;mt++)
                ldm4(ab + ((wm*64 + mt*16 + (lane&15))*GH_ALD + ks*16 + (lane>>4)*8)*2, aw[mt]);
            #pragma unroll
            for (int p=0;p<2;p++)
                ldm4t(bb + ((ks*16 + (lane&7) + ((lane>>3)&1)*8)*GH_BLD + wn*32 + p*16 + (lane>>4)*8)*2, bw[p]);
            #pragma unroll
            for (int mt=0;mt<4;mt++)
                #pragma unroll
                for (int p=0;p<2;p++){
                    mma16(acc[mt][2*p  ], aw[mt], bw[p][0], bw[p][1]);
                    mma16(acc[mt][2*p+1], aw[mt], bw[p][2], bw[p][3]);
                }
        }
        __syncthreads();
    }

    #pragma unroll
    for (int mt=0;mt<4;mt++)
        #pragma unroll
        for (int nt=0;nt<4;nt++){
            float* a = acc[mt][nt];
            int r = mBase + wm*64 + mt*16 + g;
            int c = nBase + wn*32 + nt*8 + 2*tig;
            if (EPI == 0){
                *(float2*)&Cf[(size_t)r*N + c]     = make_float2(a[0], a[1]);
                *(float2*)&Cf[(size_t)(r+8)*N + c] = make_float2(a[2], a[3]);
            } else if (EPI == 1){
                *(__half2*)&Ch[(size_t)r*N + c]     = __floats2half2_rn(a[0], a[1]);
                *(__half2*)&Ch[(size_t)(r+8)*N + c] = __floats2half2_rn(a[2], a[3]);
            } else {
                float2 bv = *(const float2*)&bias[c];
                *(__half2*)&Ch[(size_t)r*N + c] =
                    __floats2half2_rn(fmaxf(a[0]+bv.x,0.f), fmaxf(a[1]+bv.y,0.f));
                *(__half2*)&Ch[(size_t)(r+8)*N + c] =
                    __floats2half2_rn(fmaxf(a[2]+bv.x,0.f), fmaxf(a[3]+bv.y,0.f));
            }
        }
}

template<int EPI>
__global__ __launch_bounds__(256,2) void gemm_h(
    const __half* __restrict__ A, const __half* __restrict__ B,
    float* __restrict__ Cf, __half* __restrict__ Ch, const float* __restrict__ bias,
    int M, int N, int K)
{
    gemm_h_body<EPI>(A, B, Cf, Ch, bias, M, N, K, blockIdx.y*128, blockIdx.x*128);
}

__global__ __launch_bounds__(256,2) void gemm_qkv(
    const __half* __restrict__ A,
    const __half* __restrict__ B0, const __half* __restrict__ B1, const __half* __restrict__ B2,
    __half* __restrict__ C0, __half* __restrict__ C1, __half* __restrict__ C2,
    int M, int N, int K)
{
    const __half* B = (blockIdx.z==0) ? B0 : (blockIdx.z==1 ? B1 : B2);
    __half*       C = (blockIdx.z==0) ? C0 : (blockIdx.z==1 ? C1 : C2);
    gemm_h_body<1>(A, B, nullptr, C, nullptr, M, N, K, blockIdx.y*128, blockIdx.x*128);
}

// ===========================================================================
// FA2-style fp16 flash attention (R5 config, verbatim). 128 threads (4 warps),
// warp = 16 q-rows, 64-row Q tile. P in registers. Double-buffered K/V.
// ===========================================================================
#define ATL 72
#define ATT_TILE (64*ATL)
#define ATT_SMEM (5*ATT_TILE*2)

__global__ __launch_bounds__(128) void attn_h_kernel(
    const __half* __restrict__ qh, const __half* __restrict__ kh,
    const __half* __restrict__ vh, __half* __restrict__ atth)
{
    extern __shared__ __half hsm[];
    __half* Qs  = hsm;
    __half* Ksb[2] = { hsm + ATT_TILE,   hsm + 2*ATT_TILE };
    __half* Vsb[2] = { hsm + 3*ATT_TILE, hsm + 4*ATT_TILE };

    const int tid = threadIdx.x, w = tid >> 5, lane = tid & 31;
    const int g = lane >> 2, tig = lane & 3;
    const int qtile = blockIdx.x, bh = blockIdx.y;
    const int b = bh >> 3, h = bh & 7;
    const size_t rowBase = (size_t)b * LL;
    const int colBase = h * QDIM;
    const int qrow0 = qtile * 64;
    const int NT = LL/64;

    auto loadKV = [&](int buf, int t) {
        #pragma unroll
        for (int i=0;i<4;i++){
            int f = tid + i*128; int r = f>>3, c = f&7;
            cp16h(&Ksb[buf][r*ATL + c*8], &kh[(rowBase + t*64 + r)*DD + colBase + c*8]);
            cp16h(&Vsb[buf][r*ATL + c*8], &vh[(rowBase + t*64 + r)*DD + colBase + c*8]);
        }
        cp_commit();
    };

    #pragma unroll
    for (int i=0;i<4;i++){
        int f = tid + i*128; int r = f>>3, c = f&7;
        cp16h(&Qs[r*ATL + c*8], &qh[(rowBase + qrow0 + r)*DD + colBase + c*8]);
    }
    cp_commit();
    loadKV(0, 0);
    cp_wait<0>(); __syncthreads();

    uint32_t qb = s2u(Qs);
    uint32_t qf[4][4];
    #pragma unroll
    for (int ks=0;ks<4;ks++)
        ldm4(qb + ((w*16 + (lane&15))*ATL + ks*16 + (lane>>4)*8)*2, qf[ks]);

    float o[8][4];
    #pragma unroll
    for (int n=0;n<8;n++){ o[n][0]=o[n][1]=o[n][2]=o[n][3]=0.f; }
    float m0=-1e30f, m1=-1e30f, l0=0.f, l1=0.f;

    for (int kt=0; kt<NT; kt++){
        __syncthreads();
        if (kt+1 < NT){ loadKV((kt+1)&1, kt+1); cp_wait<1>(); }
        else          { cp_wait<0>(); }
        __syncthreads();

        uint32_t kb = s2u(Ksb[kt&1]);
        uint32_t vb = s2u(Vsb[kt&1]);

        // S = Q @ K^T. K frag: (lane>>3)&1 -> dim half, lane>>4 -> key half
        float s[8][4];
        #pragma unroll
        for (int n=0;n<8;n++){ s[n][0]=s[n][1]=s[n][2]=s[n][3]=0.f; }
        #pragma unroll
        for (int ks=0;ks<4;ks++){
            uint32_t bw[4][4];
            #pragma unroll
            for (int p=0;p<4;p++)
                ldm4(kb + ((p*16 + (lane&7) + (lane>>4)*8)*ATL + ks*16 + ((lane>>3)&1)*8)*2, bw[p]);
            #pragma unroll
            for (int p=0;p<4;p++){
                mma16(s[2*p  ], qf[ks], bw[p][0], bw[p][1]);
                mma16(s[2*p+1], qf[ks], bw[p][2], bw[p][3]);
            }
        }

        // online softmax (rows g / g+8)
        float mx0=-1e30f, mx1=-1e30f;
        #pragma unroll
        for (int n=0;n<8;n++){
            mx0 = fmaxf(mx0, fmaxf(s[n][0], s[n][1]));
            mx1 = fmaxf(mx1, fmaxf(s[n][2], s[n][3]));
        }
        mx0 = fmaxf(mx0, __shfl_xor_sync(0xffffffffu, mx0, 1));
        mx0 = fmaxf(mx0, __shfl_xor_sync(0xffffffffu, mx0, 2));
        mx1 = fmaxf(mx1, __shfl_xor_sync(0xffffffffu, mx1, 1));
        mx1 = fmaxf(mx1, __shfl_xor_sync(0xffffffffu, mx1, 2));
        float nm0 = fmaxf(m0, mx0*ATT_SCALE);
        float nm1 = fmaxf(m1, mx1*ATT_SCALE);
        float a0 = __expf(m0 - nm0), a1 = __expf(m1 - nm1);
        float sum0 = 0.f, sum1 = 0.f;
        #pragma unroll
        for (int n=0;n<8;n++){
            s[n][0] = __expf(s[n][0]*ATT_SCALE - nm0);
            s[n][1] = __expf(s[n][1]*ATT_SCALE - nm0);
            s[n][2] = __expf(s[n][2]*ATT_SCALE - nm1);
            s[n][3] = __expf(s[n][3]*ATT_SCALE - nm1);
            sum0 += s[n][0] + s[n][1];
            sum1 += s[n][2] + s[n][3];
        }
        sum0 += __shfl_xor_sync(0xffffffffu, sum0, 1);
        sum0 += __shfl_xor_sync(0xffffffffu, sum0, 2);
        sum1 += __shfl_xor_sync(0xffffffffu, sum1, 1);
        sum1 += __shfl_xor_sync(0xffffffffu, sum1, 2);
        l0 = l0*a0 + sum0;  l1 = l1*a1 + sum1;
        m0 = nm0;  m1 = nm1;
        #pragma unroll
        for (int n=0;n<8;n++){
            o[n][0]*=a0; o[n][1]*=a0; o[n][2]*=a1; o[n][3]*=a1;
        }

        // O += P @ V  (P repacked from S accumulators, registers only)
        #pragma unroll
        for (int ks=0;ks<4;ks++){
            uint32_t pa[4];
            pa[0] = h2u(__floats2half2_rn(s[2*ks  ][0], s[2*ks  ][1]));
            pa[1] = h2u(__floats2half2_rn(s[2*ks  ][2], s[2*ks  ][3]));
            pa[2] = h2u(__floats2half2_rn(s[2*ks+1][0], s[2*ks+1][1]));
            pa[3] = h2u(__floats2half2_rn(s[2*ks+1][2], s[2*ks+1][3]));
            uint32_t vw[4][4];
            #pragma unroll
            for (int p=0;p<4;p++)
                ldm4t(vb + ((ks*16 + (lane&7) + ((lane>>3)&1)*8)*ATL + p*16 + (lane>>4)*8)*2, vw[p]);
            #pragma unroll
            for (int p=0;p<4;p++){
                mma16(o[2*p  ], pa, vw[p][0], vw[p][1]);
                mma16(o[2*p+1], pa, vw[p][2], vw[p][3]);
            }
        }
    }

    float inv0 = 1.f/l0, inv1 = 1.f/l1;
    const size_t r0 = rowBase + qrow0 + w*16 + g;
    #pragma unroll
    for (int n=0;n<8;n++){
        *(__half2*)&atth[ r0     *DD + colBase + n*8 + 2*tig] =
            __floats2half2_rn(o[n][0]*inv0, o[n][1]*inv0);
        *(__half2*)&atth[(r0 + 8)*DD + colBase + n*8 + 2*tig] =
            __floats2half2_rn(o[n][2]*inv1, o[n][3]*inv1);
    }
}

// ===========================================================================
// LayerNorm over D=512 of (in + bias + resid); float4 vectorized.
// 128 threads, each owns one float4 (512 = 128*4). Optional fp16 copy out.
// ===========================================================================
__global__ __launch_bounds__(128) void ln_kernel(
    const float* __restrict__ in, const float* __restrict__ bias,
    const float* __restrict__ resid,
    const float* __restrict__ gamma, const float* __restrict__ beta,
    float* __restrict__ out, __half* __restrict__ out_h)
{
    __shared__ float sh[8];
    const int row = blockIdx.x;
    const size_t base = (size_t)row * DD;
    const int c = threadIdx.x * 4;

    float4 vi = *(const float4*)&in[base + c];
    float4 vb = *(const float4*)&bias[c];
    float4 vr = *(const float4*)&resid[base + c];
    float v0 = vi.x + vb.x + vr.x;
    float v1 = vi.y + vb.y + vr.y;
    float v2 = vi.z + vb.z + vr.z;
    float v3 = vi.w + vb.w + vr.w;

    float s = v0+v1+v2+v3;
    #pragma unroll
    for (int o=16;o>0;o>>=1) s += __shfl_xor_sync(0xffffffffu, s, o);
    if ((threadIdx.x & 31)==0) sh[threadIdx.x>>5] = s;
    __syncthreads();
    float mean = (sh[0]+sh[1]+sh[2]+sh[3]) * (1.0f/DD);
    float d0=v0-mean, d1=v1-mean, d2=v2-mean, d3=v3-mean;
    float sq = d0*d0 + d1*d1 + d2*d2 + d3*d3;
    #pragma unroll
    for (int o=16;o>0;o>>=1) sq += __shfl_xor_sync(0xffffffffu, sq, o);
    __syncthreads();
    if ((threadIdx.x & 31)==0) sh[4 + (threadIdx.x>>5)] = sq;
    __syncthreads();
    float var = (sh[4]+sh[5]+sh[6]+sh[7]) * (1.0f/DD);
    float rstd = rsqrtf(var + EPS);

    float4 vg = *(const float4*)&gamma[c];
    float4 vbeta = *(const float4*)&beta[c];
    float r0 = d0*rstd*vg.x + vbeta.x;
    float r1 = d1*rstd*vg.y + vbeta.y;
    float r2 = d2*rstd*vg.z + vbeta.z;
    float r3 = d3*rstd*vg.w + vbeta.w;
    *(float4*)&out[base + c] = make_float4(r0, r1, r2, r3);
    if (out_h){
        __half2 h0 = __floats2half2_rn(r0, r1);
        __half2 h1 = __floats2half2_rn(r2, r3);
        *(uint2*)&out_h[base + c] = make_uint2(h2u(h0), h2u(h1));
    }
}

// ===========================================================================
// fp32 -> fp16 convert: 7 tensors in one launch via blockIdx.y
// ===========================================================================
__global__ __launch_bounds__(256) void f2h7(
    const float* i0, __half* o0, int n0, const float* i1, __half* o1, int n1,
    const float* i2, __half* o2, int n2, const float* i3, __half* o3, int n3,
    const float* i4, __half* o4, int n4_, const float* i5, __half* o5, int n5,
    const float* i6, __half* o6, int n6)
{
    const float* in; __half* out; int n;
    switch (blockIdx.y){
        case 0: in=i0; out=o0; n=n0; break;
        case 1: in=i1; out=o1; n=n1; break;
        case 2: in=i2; out=o2; n=n2; break;
        case 3: in=i3; out=o3; n=n3; break;
        case 4: in=i4; out=o4; n=n4_; break;
        case 5: in=i5; out=o5; n=n5; break;
        default: in=i6; out=o6; n=n6; break;
    }
    int idx = blockIdx.x*256 + threadIdx.x;
    int q = n >> 2;
    if (idx < q){
        float4 v = ((const float4*)in)[idx];
        ((__half2*)out)[idx*2  ] = __floats2half2_rn(v.x, v.y);
        ((__half2*)out)[idx*2+1] = __floats2half2_rn(v.z, v.w);
    }
}

// ===========================================================================
extern "C" void kernel_launch(void* const* d_in, const int* in_sizes, int n_in,
                              void* d_out, int out_size)
{
    const float* x     = (const float*)d_in[0];
    const float* WQ    = (const float*)d_in[1];
    const float* WK    = (const float*)d_in[2];
    const float* WV    = (const float*)d_in[3];
    const float* WZ    = (const float*)d_in[4];
    const float* bZ    = (const float*)d_in[5];
    const float* W1    = (const float*)d_in[6];
    const float* b1    = (const float*)d_in[7];
    const float* W2    = (const float*)d_in[8];
    const float* b2    = (const float*)d_in[9];
    const float* gamma = (const float*)d_in[10];
    const float* beta  = (const float*)d_in[11];
    float* out = (float*)d_out;

    float  *t1, *zn, *o2;
    __half *xh,*wqh,*wkh,*wvh,*wzh,*w1h,*w2h,*qh,*kh,*vh,*atth,*znh,*hh;
    cudaGetSymbolAddress((void**)&t1,  g_t1);
    cudaGetSymbolAddress((void**)&zn,  g_zn);
    cudaGetSymbolAddress((void**)&o2,  g_o2);
    cudaGetSymbolAddress((void**)&xh,  g_xh);
    cudaGetSymbolAddress((void**)&wqh, g_wqh);
    cudaGetSymbolAddress((void**)&wkh, g_wkh);
    cudaGetSymbolAddress((void**)&wvh, g_wvh);
    cudaGetSymbolAddress((void**)&wzh, g_wzh);
    cudaGetSymbolAddress((void**)&w1h, g_w1h);
    cudaGetSymbolAddress((void**)&w2h, g_w2h);
    cudaGetSymbolAddress((void**)&qh,  g_qh);
    cudaGetSymbolAddress((void**)&kh,  g_kh);
    cudaGetSymbolAddress((void**)&vh,  g_vh);
    cudaGetSymbolAddress((void**)&atth,g_atth);
    cudaGetSymbolAddress((void**)&znh, g_znh);
    cudaGetSymbolAddress((void**)&hh,  g_hh);

    cudaFuncSetAttribute(gemm_h<0>, cudaFuncAttributeMaxDynamicSharedMemorySize, GH_SMEM);
    cudaFuncSetAttribute(gemm_h<2>, cudaFuncAttributeMaxDynamicSharedMemorySize, GH_SMEM);
    cudaFuncSetAttribute(gemm_qkv,  cudaFuncAttributeMaxDynamicSharedMemorySize, GH_SMEM);
    cudaFuncSetAttribute(attn_h_kernel, cudaFuncAttributeMaxDynamicSharedMemorySize, ATT_SMEM);

    // convert inputs + weights to fp16 (RN)
    f2h7<<<dim3(4096,7), 256>>>(
        x,  xh,  MTOT*DD,
        WQ, wqh, DD*DD,  WK, wkh, DD*DD,  WV, wvh, DD*DD,  WZ, wzh, DD*DD,
        W1, w1h, DD*FFD, W2, w2h, FFD*DD);

    // QKV projections -> fp16 q/k/v (3-way z batch)
    gemm_qkv<<<dim3(DD/128, MTOT/128, 3), 256, GH_SMEM>>>(
        xh, wqh, wkh, wvh, qh, kh, vh, MTOT, DD, DD);

    // flash attention -> fp16 att (64-row Q tiles, R5 config)
    attn_h_kernel<<<dim3(LL/64, BB*HH), 128, ATT_SMEM>>>(qh, kh, vh, atth);

    // att @ WZ -> fp32 t1
    gemm_h<0><<<dim3(DD/128, MTOT/128), 256, GH_SMEM>>>(
        atth, wzh, t1, nullptr, nullptr, MTOT, DD, DD);

    // LN1: LN(t1 + bZ + x) -> zn (fp32) + znh (fp16)
    ln_kernel<<<MTOT, 128>>>(t1, bZ, x, gamma, beta, zn, znh);

    // FF1: zn @ W1 + b1, relu -> fp16 hh
    gemm_h<2><<<dim3(FFD/128, MTOT/128), 256, GH_SMEM>>>(
        znh, w1h, nullptr, hh, b1, MTOT, FFD, DD);

    // FF2: hh @ W2 -> fp32 o2
    gemm_h<0><<<dim3(DD/128, MTOT/128), 256, GH_SMEM>>>(
        hh, w2h, o2, nullptr, nullptr, MTOT, DD, FFD);

    // LN2: LN(o2 + b2 + zn) -> out
    ln_kernel<<<MTOT, 128>>>(o2, b2, zn, gamma, beta, out, nullptr);
}